// round 1
// baseline (speedup 1.0000x reference)
#include <cuda_runtime.h>
#include <cuda_bf16.h>
#include <cstdint>

// Problem constants
#define VOCABN 50257
#define SMALLN 512
#define LARGEN 1024
#define NTOK   8192      // B*S = 4*2048

// ---------------------------------------------------------------------------
// Kernel 1: first half — out[t, 0:512] = weight[id] + residual[id, 0:512]
// Pure gather + add, float4 vectorized.
// ---------------------------------------------------------------------------
__global__ void gather_first_half(const int* __restrict__ ids,
                                  const float4* __restrict__ w4,    // [VOCAB][128]
                                  const float4* __restrict__ r4,    // [VOCAB][256]
                                  float4* __restrict__ out4) {      // [NTOK][256]
    int gid = blockIdx.x * blockDim.x + threadIdx.x;  // NTOK*128 total
    int t = gid >> 7;
    int c = gid & 127;
    int id = ids[t];
    float4 a = w4[(size_t)id * 128 + c];
    float4 b = r4[(size_t)id * 256 + c];
    float4 o;
    o.x = a.x + b.x; o.y = a.y + b.y; o.z = a.z + b.z; o.w = a.w + b.w;
    out4[(size_t)t * 256 + c] = o;
}

// ---------------------------------------------------------------------------
// Kernel 2: second half — out[t, 512+j] = sum_k weight[id,k]*cw[j,k]
//                                          + residual[id, 512+j]
// Tiled bf16 mma.sync GEMM: C[8192,512] = A_gathered[8192,512] * cw^T.
// BM=128, BN=128, BK=32, 256 threads (8 warps in 2x4), warp tile 64x32,
// per-warp 4x4 m16n8k16 mma per k-half.
// ---------------------------------------------------------------------------
#define BM 128
#define BN 128
#define BK 32
#define KPAD 36   // padded row stride in elements (72B: 8B aligned, low-conflict)

__global__ __launch_bounds__(256)
void gemm_second_half(const int* __restrict__ ids,
                      const float* __restrict__ weight,     // [VOCAB][512]
                      const float* __restrict__ cw,         // [512][512]
                      const float* __restrict__ residual,   // [VOCAB][1024]
                      float* __restrict__ out) {            // [NTOK][1024]
    __shared__ __nv_bfloat16 As[BM][KPAD];
    __shared__ __nv_bfloat16 Bs[BN][KPAD];
    __shared__ int sids[BM];

    const int bn = blockIdx.x;        // 0..3   (N tiles)
    const int bm = blockIdx.y;        // 0..63  (M tiles)
    const int tid  = threadIdx.x;
    const int warp = tid >> 5;
    const int lane = tid & 31;
    const int wm = warp >> 2;         // 0..1
    const int wn = warp & 3;          // 0..3
    const int g  = lane >> 2;         // group id 0..7
    const int tg = lane & 3;          // thread-in-group 0..3

    if (tid < BM) sids[tid] = ids[bm * BM + tid];
    __syncthreads();

    float acc[4][4][4];
    #pragma unroll
    for (int mi = 0; mi < 4; mi++)
        #pragma unroll
        for (int ni = 0; ni < 4; ni++)
            #pragma unroll
            for (int r = 0; r < 4; r++) acc[mi][ni][r] = 0.f;

    const int lrow = tid >> 3;        // 0..31
    const int lc4  = (tid & 7) * 4;   // 0,4,...,28

    for (int kt = 0; kt < SMALLN; kt += BK) {
        // --- global -> shared (fp32 -> bf16 convert) ---
        #pragma unroll
        for (int i = 0; i < 4; i++) {
            int row = lrow + i * 32;
            // A: gathered weight rows
            const float4 av = *reinterpret_cast<const float4*>(
                weight + (size_t)sids[row] * SMALLN + kt + lc4);
            As[row][lc4 + 0] = __float2bfloat16(av.x);
            As[row][lc4 + 1] = __float2bfloat16(av.y);
            As[row][lc4 + 2] = __float2bfloat16(av.z);
            As[row][lc4 + 3] = __float2bfloat16(av.w);
            // B: cw rows (Bs[n][k])
            const float4 bv = *reinterpret_cast<const float4*>(
                cw + (size_t)(bn * BN + row) * SMALLN + kt + lc4);
            Bs[row][lc4 + 0] = __float2bfloat16(bv.x);
            Bs[row][lc4 + 1] = __float2bfloat16(bv.y);
            Bs[row][lc4 + 2] = __float2bfloat16(bv.z);
            Bs[row][lc4 + 3] = __float2bfloat16(bv.w);
        }
        __syncthreads();

        // --- two k16 halves ---
        #pragma unroll
        for (int kh = 0; kh < 2; kh++) {
            const int kk = kh * 16;
            uint32_t af[4][4], bf[4][2];
            #pragma unroll
            for (int mi = 0; mi < 4; mi++) {
                int r0 = wm * 64 + mi * 16;
                af[mi][0] = *reinterpret_cast<const uint32_t*>(&As[r0 + g    ][kk + tg * 2    ]);
                af[mi][1] = *reinterpret_cast<const uint32_t*>(&As[r0 + g + 8][kk + tg * 2    ]);
                af[mi][2] = *reinterpret_cast<const uint32_t*>(&As[r0 + g    ][kk + tg * 2 + 8]);
                af[mi][3] = *reinterpret_cast<const uint32_t*>(&As[r0 + g + 8][kk + tg * 2 + 8]);
            }
            #pragma unroll
            for (int ni = 0; ni < 4; ni++) {
                int n0 = wn * 32 + ni * 8;
                bf[ni][0] = *reinterpret_cast<const uint32_t*>(&Bs[n0 + g][kk + tg * 2    ]);
                bf[ni][1] = *reinterpret_cast<const uint32_t*>(&Bs[n0 + g][kk + tg * 2 + 8]);
            }
            #pragma unroll
            for (int mi = 0; mi < 4; mi++)
                #pragma unroll
                for (int ni = 0; ni < 4; ni++) {
                    asm volatile(
                        "mma.sync.aligned.m16n8k16.row.col.f32.bf16.bf16.f32 "
                        "{%0,%1,%2,%3}, {%4,%5,%6,%7}, {%8,%9}, {%0,%1,%2,%3};\n"
                        : "+f"(acc[mi][ni][0]), "+f"(acc[mi][ni][1]),
                          "+f"(acc[mi][ni][2]), "+f"(acc[mi][ni][3])
                        : "r"(af[mi][0]), "r"(af[mi][1]), "r"(af[mi][2]), "r"(af[mi][3]),
                          "r"(bf[ni][0]), "r"(bf[ni][1]));
                }
        }
        __syncthreads();
    }

    // --- epilogue: + residual[id, 512+col], store to out[t, 512+col] ---
    #pragma unroll
    for (int mi = 0; mi < 4; mi++) {
        const int lr0 = wm * 64 + mi * 16 + g;     // local row in tile
        const int t0  = bm * BM + lr0;
        const int id0 = sids[lr0];
        const int id1 = sids[lr0 + 8];
        #pragma unroll
        for (int ni = 0; ni < 4; ni++) {
            const int col = bn * BN + wn * 32 + ni * 8 + tg * 2;   // 0..511
            // row lr0
            {
                float2 rv = *reinterpret_cast<const float2*>(
                    residual + (size_t)id0 * LARGEN + SMALLN + col);
                float2 o;
                o.x = acc[mi][ni][0] + rv.x;
                o.y = acc[mi][ni][1] + rv.y;
                *reinterpret_cast<float2*>(
                    out + (size_t)t0 * LARGEN + SMALLN + col) = o;
            }
            // row lr0 + 8
            {
                float2 rv = *reinterpret_cast<const float2*>(
                    residual + (size_t)id1 * LARGEN + SMALLN + col);
                float2 o;
                o.x = acc[mi][ni][2] + rv.x;
                o.y = acc[mi][ni][3] + rv.y;
                *reinterpret_cast<float2*>(
                    out + (size_t)(t0 + 8) * LARGEN + SMALLN + col) = o;
            }
        }
    }
}

// ---------------------------------------------------------------------------
// Launch
// ---------------------------------------------------------------------------
extern "C" void kernel_launch(void* const* d_in, const int* in_sizes, int n_in,
                              void* d_out, int out_size) {
    const int*   ids      = (const int*)  d_in[0];  // [4,2048] int32
    const float* weight   = (const float*)d_in[1];  // [50257,512]
    const float* cw       = (const float*)d_in[2];  // [512,512]
    const float* residual = (const float*)d_in[3];  // [50257,1024]
    float* out = (float*)d_out;                     // [8192,1024]

    // First half: gather + add (float4)
    {
        int total = NTOK * (SMALLN / 4);            // 1,048,576 float4 ops
        int threads = 256;
        int blocks = total / threads;
        gather_first_half<<<blocks, threads>>>(
            ids,
            reinterpret_cast<const float4*>(weight),
            reinterpret_cast<const float4*>(residual),
            reinterpret_cast<float4*>(out));
    }

    // Second half: gathered GEMM + residual
    {
        dim3 grid(SMALLN / BN, NTOK / BM);          // (4, 64)
        gemm_second_half<<<grid, 256>>>(ids, weight, cw, residual, out);
    }
}

// round 2
// speedup vs baseline: 1.4742x; 1.4742x over previous
#include <cuda_runtime.h>
#include <cuda_bf16.h>
#include <cstdint>

// Problem constants
#define VOCABN 50257
#define SMALLN 512
#define LARGEN 1024
#define NTOK   8192      // B*S = 4*2048

// bf16 staging buffers (device globals: allocation-free scratch)
__device__ __nv_bfloat16 g_Abf[NTOK * SMALLN];    // gathered weight rows, bf16
__device__ __nv_bfloat16 g_Bbf[SMALLN * SMALLN];  // cw, bf16

// ---------------------------------------------------------------------------
// Kernel 1: first half — out[t,0:512] = weight[id] + residual[id,0:512]
// ALSO stages bf16(weight[id]) into g_Abf for the GEMM (free: row already read)
// ---------------------------------------------------------------------------
__global__ void gather_first_half(const int* __restrict__ ids,
                                  const float4* __restrict__ w4,    // [VOCAB][128]
                                  const float4* __restrict__ r4,    // [VOCAB][256]
                                  float4* __restrict__ out4) {      // [NTOK][256]
    int gid = blockIdx.x * blockDim.x + threadIdx.x;  // NTOK*128 total
    int t = gid >> 7;
    int c = gid & 127;
    int id = ids[t];
    float4 a = w4[(size_t)id * 128 + c];
    float4 b = r4[(size_t)id * 256 + c];
    float4 o;
    o.x = a.x + b.x; o.y = a.y + b.y; o.z = a.z + b.z; o.w = a.w + b.w;
    out4[(size_t)t * 256 + c] = o;

    // bf16 A staging (8B store)
    __nv_bfloat162 p0 = {__float2bfloat16(a.x), __float2bfloat16(a.y)};
    __nv_bfloat162 p1 = {__float2bfloat16(a.z), __float2bfloat16(a.w)};
    __nv_bfloat162* ap = reinterpret_cast<__nv_bfloat162*>(
        g_Abf + (size_t)t * SMALLN + c * 4);
    ap[0] = p0;
    ap[1] = p1;
}

// ---------------------------------------------------------------------------
// Kernel 1b: cw -> bf16 (tiny, 0.5 MB output)
// ---------------------------------------------------------------------------
__global__ void convert_cw(const float4* __restrict__ cw4) {
    int i = blockIdx.x * blockDim.x + threadIdx.x;   // 65536 total
    float4 v = cw4[i];
    __nv_bfloat162 p0 = {__float2bfloat16(v.x), __float2bfloat16(v.y)};
    __nv_bfloat162 p1 = {__float2bfloat16(v.z), __float2bfloat16(v.w)};
    __nv_bfloat162* bp = reinterpret_cast<__nv_bfloat162*>(g_Bbf + (size_t)i * 4);
    bp[0] = p0;
    bp[1] = p1;
}

// ---------------------------------------------------------------------------
// Kernel 2: second half — C[8192,512] = Abf @ Bbf^T (+ residual gather)
// 3-stage cp.async pipelined bf16 mma.sync GEMM.
// BM=128, BN=128, BK=64, 256 threads (8 warps 2x4), warp tile 64x32.
// ---------------------------------------------------------------------------
#define BM 128
#define BN 128
#define BK 64
#define KP 72                       // padded smem row stride (bf16 elems)
#define STAGES 3
#define ASZ (BM * KP)               // elems per A stage
#define BSZ (BN * KP)
#define STAGE_ELEMS (ASZ + BSZ)
#define SMEM_BYTES (STAGES * STAGE_ELEMS * 2)

__device__ __forceinline__ void cpa16(void* sm, const void* g) {
    uint32_t s = (uint32_t)__cvta_generic_to_shared(sm);
    asm volatile("cp.async.cg.shared.global [%0], [%1], 16;\n" :: "r"(s), "l"(g));
}

__global__ __launch_bounds__(256)
void gemm_second_half(const int* __restrict__ ids,
                      const float* __restrict__ residual,   // [VOCAB][1024]
                      float* __restrict__ out) {            // [NTOK][1024]
    extern __shared__ __nv_bfloat16 smem[];
    __shared__ int sids[BM];

    const int bn = blockIdx.x;        // 0..3
    const int bm = blockIdx.y;        // 0..63
    const int tid  = threadIdx.x;
    const int warp = tid >> 5;
    const int lane = tid & 31;
    const int wm = warp >> 2;         // 0..1
    const int wn = warp & 3;          // 0..3
    const int g  = lane >> 2;         // 0..7
    const int tg = lane & 3;          // 0..3

    if (tid < BM) sids[tid] = ids[bm * BM + tid];

    // ---- stage loader: 128 rows x 64 bf16 (8x16B chunks per row), A and B ----
    const int lrow = tid >> 1;                 // with i*... see below
    auto load_stage = [&](int s, int kt) {
        __nv_bfloat16* As = smem + s * STAGE_ELEMS;
        __nv_bfloat16* Bs = As + ASZ;
        #pragma unroll
        for (int i = 0; i < 4; i++) {
            int c   = tid + i * 256;           // 0..1023
            int row = c >> 3;                  // 0..127
            int kc  = (c & 7) * 8;             // bf16 offset within BK
            cpa16(As + row * KP + kc,
                  g_Abf + (size_t)(bm * BM + row) * SMALLN + kt + kc);
            cpa16(Bs + row * KP + kc,
                  g_Bbf + (size_t)(bn * BN + row) * SMALLN + kt + kc);
        }
    };
    (void)lrow;

    float acc[4][4][4];
    #pragma unroll
    for (int mi = 0; mi < 4; mi++)
        #pragma unroll
        for (int ni = 0; ni < 4; ni++)
            #pragma unroll
            for (int r = 0; r < 4; r++) acc[mi][ni][r] = 0.f;

    // ---- prologue: fill 2 stages ----
    load_stage(0, 0);
    asm volatile("cp.async.commit_group;\n");
    load_stage(1, BK);
    asm volatile("cp.async.commit_group;\n");

    // ---- mainloop: 8 K-tiles ----
    #pragma unroll 1
    for (int kt8 = 0; kt8 < 8; kt8++) {
        asm volatile("cp.async.wait_group 1;\n");
        __syncthreads();   // all threads done with stage (kt8+2)%3 from iter kt8-1

        if (kt8 + 2 < 8) load_stage((kt8 + 2) % STAGES, (kt8 + 2) * BK);
        asm volatile("cp.async.commit_group;\n");

        const __nv_bfloat16* As = smem + (kt8 % STAGES) * STAGE_ELEMS;
        const __nv_bfloat16* Bs = As + ASZ;

        #pragma unroll
        for (int kh = 0; kh < 4; kh++) {
            const int kk = kh * 16;
            uint32_t af[4][4], bf[4][2];
            #pragma unroll
            for (int mi = 0; mi < 4; mi++) {
                int r0 = wm * 64 + mi * 16;
                af[mi][0] = *reinterpret_cast<const uint32_t*>(As + (r0 + g    ) * KP + kk + tg * 2    );
                af[mi][1] = *reinterpret_cast<const uint32_t*>(As + (r0 + g + 8) * KP + kk + tg * 2    );
                af[mi][2] = *reinterpret_cast<const uint32_t*>(As + (r0 + g    ) * KP + kk + tg * 2 + 8);
                af[mi][3] = *reinterpret_cast<const uint32_t*>(As + (r0 + g + 8) * KP + kk + tg * 2 + 8);
            }
            #pragma unroll
            for (int ni = 0; ni < 4; ni++) {
                int n0 = wn * 32 + ni * 8;
                bf[ni][0] = *reinterpret_cast<const uint32_t*>(Bs + (n0 + g) * KP + kk + tg * 2    );
                bf[ni][1] = *reinterpret_cast<const uint32_t*>(Bs + (n0 + g) * KP + kk + tg * 2 + 8);
            }
            #pragma unroll
            for (int mi = 0; mi < 4; mi++)
                #pragma unroll
                for (int ni = 0; ni < 4; ni++) {
                    asm volatile(
                        "mma.sync.aligned.m16n8k16.row.col.f32.bf16.bf16.f32 "
                        "{%0,%1,%2,%3}, {%4,%5,%6,%7}, {%8,%9}, {%0,%1,%2,%3};\n"
                        : "+f"(acc[mi][ni][0]), "+f"(acc[mi][ni][1]),
                          "+f"(acc[mi][ni][2]), "+f"(acc[mi][ni][3])
                        : "r"(af[mi][0]), "r"(af[mi][1]), "r"(af[mi][2]), "r"(af[mi][3]),
                          "r"(bf[ni][0]), "r"(bf[ni][1]));
                }
        }
    }

    // ---- epilogue: + residual[id, 512+col] -> out[t, 512+col] ----
    #pragma unroll
    for (int mi = 0; mi < 4; mi++) {
        const int lr0 = wm * 64 + mi * 16 + g;
        const int t0  = bm * BM + lr0;
        const int id0 = sids[lr0];
        const int id1 = sids[lr0 + 8];
        #pragma unroll
        for (int ni = 0; ni < 4; ni++) {
            const int col = bn * BN + wn * 32 + ni * 8 + tg * 2;
            {
                float2 rv = *reinterpret_cast<const float2*>(
                    residual + (size_t)id0 * LARGEN + SMALLN + col);
                float2 o;
                o.x = acc[mi][ni][0] + rv.x;
                o.y = acc[mi][ni][1] + rv.y;
                *reinterpret_cast<float2*>(
                    out + (size_t)t0 * LARGEN + SMALLN + col) = o;
            }
            {
                float2 rv = *reinterpret_cast<const float2*>(
                    residual + (size_t)id1 * LARGEN + SMALLN + col);
                float2 o;
                o.x = acc[mi][ni][2] + rv.x;
                o.y = acc[mi][ni][3] + rv.y;
                *reinterpret_cast<float2*>(
                    out + (size_t)(t0 + 8) * LARGEN + SMALLN + col) = o;
            }
        }
    }
}

// ---------------------------------------------------------------------------
// Launch
// ---------------------------------------------------------------------------
extern "C" void kernel_launch(void* const* d_in, const int* in_sizes, int n_in,
                              void* d_out, int out_size) {
    const int*   ids      = (const int*)  d_in[0];  // [4,2048]
    const float* weight   = (const float*)d_in[1];  // [50257,512]
    const float* cw       = (const float*)d_in[2];  // [512,512]
    const float* residual = (const float*)d_in[3];  // [50257,1024]
    float* out = (float*)d_out;                     // [8192,1024]

    cudaFuncSetAttribute(gemm_second_half,
                         cudaFuncAttributeMaxDynamicSharedMemorySize, SMEM_BYTES);

    // cw -> bf16 (independent)
    convert_cw<<<(SMALLN * SMALLN / 4) / 256, 256>>>(
        reinterpret_cast<const float4*>(cw));

    // first half gather+add + A bf16 staging
    {
        int total = NTOK * (SMALLN / 4);
        gather_first_half<<<total / 256, 256>>>(
            ids,
            reinterpret_cast<const float4*>(weight),
            reinterpret_cast<const float4*>(residual),
            reinterpret_cast<float4*>(out));
    }

    // pipelined GEMM + residual epilogue
    {
        dim3 grid(SMALLN / BN, NTOK / BM);   // (4, 64)
        gemm_second_half<<<grid, 256, SMEM_BYTES>>>(ids, residual, out);
    }
}

// round 3
// speedup vs baseline: 1.5530x; 1.0535x over previous
#include <cuda_runtime.h>
#include <cuda_bf16.h>
#include <cstdint>

// Problem constants
#define VOCABN 50257
#define SMALLN 512
#define LARGEN 1024
#define NTOK   8192      // B*S = 4*2048

// bf16 staging buffers (device globals: allocation-free scratch)
__device__ __nv_bfloat16 g_Abf[NTOK * SMALLN];    // gathered weight rows, bf16
__device__ __nv_bfloat16 g_Bbf[SMALLN * SMALLN];  // cw, bf16

// ---------------------------------------------------------------------------
// Kernel 1 (merged prep):
//   gids [0, NTOK*128):   out[t,0:512] = weight[id] + residual[id,0:512]
//                         + stage bf16(weight[id]) into g_Abf
//   gids [NTOK*128, +64K): g_Bbf = bf16(cw)
// ---------------------------------------------------------------------------
#define GATHER_UNITS (NTOK * 128)       // float4 units for gather
#define CW_UNITS     (SMALLN * SMALLN / 4)

__global__ void prep_kernel(const int* __restrict__ ids,
                            const float4* __restrict__ w4,    // [VOCAB][128]
                            const float4* __restrict__ r4,    // [VOCAB][256]
                            const float4* __restrict__ cw4,   // [512][128]
                            float4* __restrict__ out4) {      // [NTOK][256]
    int gid = blockIdx.x * blockDim.x + threadIdx.x;
    if (gid < GATHER_UNITS) {
        int t = gid >> 7;
        int c = gid & 127;
        int id = ids[t];
        float4 a = w4[(size_t)id * 128 + c];
        float4 b = r4[(size_t)id * 256 + c];
        float4 o;
        o.x = a.x + b.x; o.y = a.y + b.y; o.z = a.z + b.z; o.w = a.w + b.w;
        out4[(size_t)t * 256 + c] = o;

        __nv_bfloat162 p0 = {__float2bfloat16(a.x), __float2bfloat16(a.y)};
        __nv_bfloat162 p1 = {__float2bfloat16(a.z), __float2bfloat16(a.w)};
        __nv_bfloat162* ap = reinterpret_cast<__nv_bfloat162*>(
            g_Abf + (size_t)t * SMALLN + c * 4);
        ap[0] = p0;
        ap[1] = p1;
    } else {
        int i = gid - GATHER_UNITS;     // 0..65535
        float4 v = cw4[i];
        __nv_bfloat162 p0 = {__float2bfloat16(v.x), __float2bfloat16(v.y)};
        __nv_bfloat162 p1 = {__float2bfloat16(v.z), __float2bfloat16(v.w)};
        __nv_bfloat162* bp = reinterpret_cast<__nv_bfloat162*>(g_Bbf + (size_t)i * 4);
        bp[0] = p0;
        bp[1] = p1;
    }
}

// ---------------------------------------------------------------------------
// Kernel 2: C[8192,512] = Abf @ Bbf^T (+ residual gather epilogue)
// 3-stage cp.async pipelined bf16 mma.sync GEMM.
// BM=256, BN=128, BK=64, 512 threads (16 warps, 4x4), warp tile 64x32.
// Grid (4, 32) = 128 CTAs -> exactly one wave on 148 SMs.
// ---------------------------------------------------------------------------
#define BM 256
#define BN 128
#define BK 64
#define KP 72                       // padded smem row stride (bf16 elems)
#define STAGES 3
#define ASZ (BM * KP)
#define BSZ (BN * KP)
#define STAGE_ELEMS (ASZ + BSZ)
#define SMEM_BYTES (STAGES * STAGE_ELEMS * 2)   // 165,888 B

__device__ __forceinline__ void cpa16(void* sm, const void* g) {
    uint32_t s = (uint32_t)__cvta_generic_to_shared(sm);
    asm volatile("cp.async.cg.shared.global [%0], [%1], 16;\n" :: "r"(s), "l"(g));
}

__global__ __launch_bounds__(512, 1)
void gemm_second_half(const int* __restrict__ ids,
                      const float* __restrict__ residual,   // [VOCAB][1024]
                      float* __restrict__ out) {            // [NTOK][1024]
    extern __shared__ __nv_bfloat16 smem[];
    __shared__ int sids[BM];

    const int bn = blockIdx.x;        // 0..3
    const int bm = blockIdx.y;        // 0..31
    const int tid  = threadIdx.x;
    const int warp = tid >> 5;
    const int lane = tid & 31;
    const int wm = warp >> 2;         // 0..3  (64-row slab)
    const int wn = warp & 3;          // 0..3  (32-col slab)
    const int g  = lane >> 2;         // 0..7
    const int tg = lane & 3;          // 0..3

    if (tid < BM) sids[tid] = ids[bm * BM + tid];

    // ---- stage loader: A 256x64, B 128x64 bf16, 16B cp.async chunks ----
    auto load_stage = [&](int s, int kt) {
        __nv_bfloat16* As = smem + s * STAGE_ELEMS;
        __nv_bfloat16* Bs = As + ASZ;
        #pragma unroll
        for (int i = 0; i < 4; i++) {                // A: 2048 chunks
            int c   = tid + i * 512;
            int row = c >> 3;
            int kc  = (c & 7) * 8;
            cpa16(As + row * KP + kc,
                  g_Abf + (size_t)(bm * BM + row) * SMALLN + kt + kc);
        }
        #pragma unroll
        for (int i = 0; i < 2; i++) {                // B: 1024 chunks
            int c   = tid + i * 512;
            int row = c >> 3;
            int kc  = (c & 7) * 8;
            cpa16(Bs + row * KP + kc,
                  g_Bbf + (size_t)(bn * BN + row) * SMALLN + kt + kc);
        }
    };

    float acc[4][4][4];
    #pragma unroll
    for (int mi = 0; mi < 4; mi++)
        #pragma unroll
        for (int ni = 0; ni < 4; ni++)
            #pragma unroll
            for (int r = 0; r < 4; r++) acc[mi][ni][r] = 0.f;

    // ---- prologue: fill 2 stages ----
    load_stage(0, 0);
    asm volatile("cp.async.commit_group;\n");
    load_stage(1, BK);
    asm volatile("cp.async.commit_group;\n");

    // ---- mainloop: 8 K-tiles ----
    #pragma unroll 1
    for (int kt8 = 0; kt8 < 8; kt8++) {
        asm volatile("cp.async.wait_group 1;\n");
        __syncthreads();

        if (kt8 + 2 < 8) load_stage((kt8 + 2) % STAGES, (kt8 + 2) * BK);
        asm volatile("cp.async.commit_group;\n");

        const __nv_bfloat16* As = smem + (kt8 % STAGES) * STAGE_ELEMS;
        const __nv_bfloat16* Bs = As + ASZ;

        #pragma unroll
        for (int kh = 0; kh < 4; kh++) {
            const int kk = kh * 16;
            uint32_t af[4][4], bf[4][2];
            #pragma unroll
            for (int mi = 0; mi < 4; mi++) {
                int r0 = wm * 64 + mi * 16;
                af[mi][0] = *reinterpret_cast<const uint32_t*>(As + (r0 + g    ) * KP + kk + tg * 2    );
                af[mi][1] = *reinterpret_cast<const uint32_t*>(As + (r0 + g + 8) * KP + kk + tg * 2    );
                af[mi][2] = *reinterpret_cast<const uint32_t*>(As + (r0 + g    ) * KP + kk + tg * 2 + 8);
                af[mi][3] = *reinterpret_cast<const uint32_t*>(As + (r0 + g + 8) * KP + kk + tg * 2 + 8);
            }
            #pragma unroll
            for (int ni = 0; ni < 4; ni++) {
                int n0 = wn * 32 + ni * 8;
                bf[ni][0] = *reinterpret_cast<const uint32_t*>(Bs + (n0 + g) * KP + kk + tg * 2    );
                bf[ni][1] = *reinterpret_cast<const uint32_t*>(Bs + (n0 + g) * KP + kk + tg * 2 + 8);
            }
            #pragma unroll
            for (int mi = 0; mi < 4; mi++)
                #pragma unroll
                for (int ni = 0; ni < 4; ni++) {
                    asm volatile(
                        "mma.sync.aligned.m16n8k16.row.col.f32.bf16.bf16.f32 "
                        "{%0,%1,%2,%3}, {%4,%5,%6,%7}, {%8,%9}, {%0,%1,%2,%3};\n"
                        : "+f"(acc[mi][ni][0]), "+f"(acc[mi][ni][1]),
                          "+f"(acc[mi][ni][2]), "+f"(acc[mi][ni][3])
                        : "r"(af[mi][0]), "r"(af[mi][1]), "r"(af[mi][2]), "r"(af[mi][3]),
                          "r"(bf[ni][0]), "r"(bf[ni][1]));
                }
        }
    }

    // ---- epilogue: + residual[id, 512+col] -> out[t, 512+col] ----
    #pragma unroll
    for (int mi = 0; mi < 4; mi++) {
        const int lr0 = wm * 64 + mi * 16 + g;
        const int t0  = bm * BM + lr0;
        const int id0 = sids[lr0];
        const int id1 = sids[lr0 + 8];
        #pragma unroll
        for (int ni = 0; ni < 4; ni++) {
            const int col = bn * BN + wn * 32 + ni * 8 + tg * 2;
            {
                float2 rv = *reinterpret_cast<const float2*>(
                    residual + (size_t)id0 * LARGEN + SMALLN + col);
                float2 o;
                o.x = acc[mi][ni][0] + rv.x;
                o.y = acc[mi][ni][1] + rv.y;
                *reinterpret_cast<float2*>(
                    out + (size_t)t0 * LARGEN + SMALLN + col) = o;
            }
            {
                float2 rv = *reinterpret_cast<const float2*>(
                    residual + (size_t)id1 * LARGEN + SMALLN + col);
                float2 o;
                o.x = acc[mi][ni][2] + rv.x;
                o.y = acc[mi][ni][3] + rv.y;
                *reinterpret_cast<float2*>(
                    out + (size_t)(t0 + 8) * LARGEN + SMALLN + col) = o;
            }
        }
    }
}

// ---------------------------------------------------------------------------
// Launch
// ---------------------------------------------------------------------------
extern "C" void kernel_launch(void* const* d_in, const int* in_sizes, int n_in,
                              void* d_out, int out_size) {
    const int*   ids      = (const int*)  d_in[0];  // [4,2048]
    const float* weight   = (const float*)d_in[1];  // [50257,512]
    const float* cw       = (const float*)d_in[2];  // [512,512]
    const float* residual = (const float*)d_in[3];  // [50257,1024]
    float* out = (float*)d_out;                     // [8192,1024]

    cudaFuncSetAttribute(gemm_second_half,
                         cudaFuncAttributeMaxDynamicSharedMemorySize, SMEM_BYTES);

    // merged prep: gather+add first half, stage Abf, convert cw
    {
        int total = GATHER_UNITS + CW_UNITS;        // 1,114,112
        prep_kernel<<<total / 256, 256>>>(
            ids,
            reinterpret_cast<const float4*>(weight),
            reinterpret_cast<const float4*>(residual),
            reinterpret_cast<const float4*>(cw),
            reinterpret_cast<float4*>(out));
    }

    // pipelined GEMM + residual epilogue (one wave: 128 CTAs)
    {
        dim3 grid(SMALLN / BN, NTOK / BM);          // (4, 32)
        gemm_second_half<<<grid, 512, SMEM_BYTES>>>(ids, residual, out);
    }
}

// round 5
// speedup vs baseline: 1.6524x; 1.0640x over previous
#include <cuda_runtime.h>
#include <cuda_bf16.h>
#include <cstdint>

// Problem constants
#define VOCABN 50257
#define SMALLN 512
#define LARGEN 1024
#define NTOK   8192      // B*S = 4*2048

// bf16 staging buffers (device globals: allocation-free scratch)
__device__ __nv_bfloat16 g_Abf[NTOK * SMALLN];    // gathered weight rows, bf16
__device__ __nv_bfloat16 g_Bbf[SMALLN * SMALLN];  // cw, bf16

// ---------------------------------------------------------------------------
// Kernel 1 (merged prep): first-half gather+add, A bf16 staging, cw bf16
// ---------------------------------------------------------------------------
#define GATHER_UNITS (NTOK * 128)
#define CW_UNITS     (SMALLN * SMALLN / 4)

__global__ void prep_kernel(const int* __restrict__ ids,
                            const float4* __restrict__ w4,
                            const float4* __restrict__ r4,
                            const float4* __restrict__ cw4,
                            float4* __restrict__ out4) {
    int gid = blockIdx.x * blockDim.x + threadIdx.x;
    if (gid < GATHER_UNITS) {
        int t = gid >> 7;
        int c = gid & 127;
        int id = ids[t];
        float4 a = w4[(size_t)id * 128 + c];
        float4 b = r4[(size_t)id * 256 + c];
        float4 o;
        o.x = a.x + b.x; o.y = a.y + b.y; o.z = a.z + b.z; o.w = a.w + b.w;
        out4[(size_t)t * 256 + c] = o;

        __nv_bfloat162 p0 = {__float2bfloat16(a.x), __float2bfloat16(a.y)};
        __nv_bfloat162 p1 = {__float2bfloat16(a.z), __float2bfloat16(a.w)};
        __nv_bfloat162* ap = reinterpret_cast<__nv_bfloat162*>(
            g_Abf + (size_t)t * SMALLN + c * 4);
        ap[0] = p0;
        ap[1] = p1;
    } else {
        int i = gid - GATHER_UNITS;
        float4 v = cw4[i];
        __nv_bfloat162 p0 = {__float2bfloat16(v.x), __float2bfloat16(v.y)};
        __nv_bfloat162 p1 = {__float2bfloat16(v.z), __float2bfloat16(v.w)};
        __nv_bfloat162* bp = reinterpret_cast<__nv_bfloat162*>(g_Bbf + (size_t)i * 4);
        bp[0] = p0;
        bp[1] = p1;
    }
}

// ---------------------------------------------------------------------------
// Kernel 2: C[8192,512] = Abf @ Bbf^T (+ residual gather epilogue)
// 3-stage cp.async pipelined bf16 mma.sync GEMM with ldmatrix fragment loads.
// BM=256, BN=128, BK=64, 512 threads (16 warps 4x4), warp tile 64x32.
// Grid (4, 32) = 128 CTAs = one wave on 148 SMs.
// ---------------------------------------------------------------------------
#define BM 256
#define BN 128
#define BK 64
#define KP 72                       // padded smem row stride (bf16 elems); 144B
#define STAGES 3
#define ASZ (BM * KP)
#define BSZ (BN * KP)
#define STAGE_ELEMS (ASZ + BSZ)
#define SMEM_BYTES (STAGES * STAGE_ELEMS * 2)   // 165,888 B

__device__ __forceinline__ void cpa16(void* sm, const void* g) {
    uint32_t s = (uint32_t)__cvta_generic_to_shared(sm);
    asm volatile("cp.async.cg.shared.global [%0], [%1], 16;\n" :: "r"(s), "l"(g));
}
__device__ __forceinline__ void ldsm_x4(uint32_t& d0, uint32_t& d1,
                                        uint32_t& d2, uint32_t& d3, uint32_t a) {
    asm volatile("ldmatrix.sync.aligned.m8n8.x4.shared.b16 {%0,%1,%2,%3}, [%4];"
                 : "=r"(d0), "=r"(d1), "=r"(d2), "=r"(d3) : "r"(a));
}

__global__ __launch_bounds__(512, 1)
void gemm_second_half(const int* __restrict__ ids,
                      const float* __restrict__ residual,   // [VOCAB][1024]
                      float* __restrict__ out) {            // [NTOK][1024]
    extern __shared__ __nv_bfloat16 smem[];
    __shared__ int sids[BM];

    const int bn = blockIdx.x;        // 0..3
    const int bm = blockIdx.y;        // 0..31
    const int tid  = threadIdx.x;
    const int warp = tid >> 5;
    const int lane = tid & 31;
    const int wm = warp >> 2;         // 0..3  (64-row slab)
    const int wn = warp & 3;          // 0..3  (32-col slab)
    const int g  = lane >> 2;         // 0..7
    const int tg = lane & 3;          // 0..3

    if (tid < BM) sids[tid] = ids[bm * BM + tid];

    // smem base addresses (32-bit shared-space)
    const uint32_t smem_b = (uint32_t)__cvta_generic_to_shared(smem);

    // ldmatrix per-lane offsets (bytes), relative to fragment origin.
    // A x4 at (r0,kk): row = r0 + (lane&15), col = kk + ((lane>>4)<<3)
    const uint32_t a_off = (uint32_t)(((lane & 15) * KP + ((lane >> 4) << 3)) * 2);
    // B x4 at (n0,kk): row = n0 + (lane&7) + ((lane>>4)<<3),
    //                  col = kk + (((lane>>3)&1)<<3)
    const uint32_t b_off = (uint32_t)((((lane & 7) + ((lane >> 4) << 3)) * KP +
                                      (((lane >> 3) & 1) << 3)) * 2);

    // ---- stage loader: A 256x64, B 128x64 bf16, 16B cp.async chunks ----
    auto load_stage = [&](int s, int kt) {
        __nv_bfloat16* As = smem + s * STAGE_ELEMS;
        __nv_bfloat16* Bs = As + ASZ;
        #pragma unroll
        for (int i = 0; i < 4; i++) {                // A: 2048 chunks
            int c   = tid + i * 512;
            int row = c >> 3;
            int kc  = (c & 7) * 8;
            cpa16(As + row * KP + kc,
                  g_Abf + (size_t)(bm * BM + row) * SMALLN + kt + kc);
        }
        #pragma unroll
        for (int i = 0; i < 2; i++) {                // B: 1024 chunks
            int c   = tid + i * 512;
            int row = c >> 3;
            int kc  = (c & 7) * 8;
            cpa16(Bs + row * KP + kc,
                  g_Bbf + (size_t)(bn * BN + row) * SMALLN + kt + kc);
        }
    };

    float acc[4][4][4];
    #pragma unroll
    for (int mi = 0; mi < 4; mi++)
        #pragma unroll
        for (int ni = 0; ni < 4; ni++)
            #pragma unroll
            for (int r = 0; r < 4; r++) acc[mi][ni][r] = 0.f;

    // ---- prologue: fill 2 stages ----
    load_stage(0, 0);
    asm volatile("cp.async.commit_group;\n");
    load_stage(1, BK);
    asm volatile("cp.async.commit_group;\n");

    // ---- mainloop: 8 K-tiles ----
    #pragma unroll 1
    for (int kt8 = 0; kt8 < 8; kt8++) {
        asm volatile("cp.async.wait_group 1;\n");
        __syncthreads();

        if (kt8 + 2 < 8) load_stage((kt8 + 2) % STAGES, (kt8 + 2) * BK);
        asm volatile("cp.async.commit_group;\n");

        const uint32_t As = smem_b + (uint32_t)((kt8 % STAGES) * STAGE_ELEMS) * 2;
        const uint32_t Bs = As + ASZ * 2;

        #pragma unroll
        for (int kh = 0; kh < 4; kh++) {
            const int kk = kh * 16;
            uint32_t af[4][4], bf[4][2];
            // A fragments: 4 x ldmatrix.x4
            #pragma unroll
            for (int mi = 0; mi < 4; mi++) {
                int r0 = wm * 64 + mi * 16;
                ldsm_x4(af[mi][0], af[mi][1], af[mi][2], af[mi][3],
                        As + a_off + (uint32_t)((r0 * KP + kk) * 2));
            }
            // B fragments: 2 x ldmatrix.x4 (each covers two ni blocks)
            #pragma unroll
            for (int nb = 0; nb < 2; nb++) {
                int n0 = wn * 32 + nb * 16;
                ldsm_x4(bf[nb * 2][0], bf[nb * 2][1],
                        bf[nb * 2 + 1][0], bf[nb * 2 + 1][1],
                        Bs + b_off + (uint32_t)((n0 * KP + kk) * 2));
            }
            #pragma unroll
            for (int mi = 0; mi < 4; mi++)
                #pragma unroll
                for (int ni = 0; ni < 4; ni++) {
                    asm volatile(
                        "mma.sync.aligned.m16n8k16.row.col.f32.bf16.bf16.f32 "
                        "{%0,%1,%2,%3}, {%4,%5,%6,%7}, {%8,%9}, {%0,%1,%2,%3};\n"
                        : "+f"(acc[mi][ni][0]), "+f"(acc[mi][ni][1]),
                          "+f"(acc[mi][ni][2]), "+f"(acc[mi][ni][3])
                        : "r"(af[mi][0]), "r"(af[mi][1]), "r"(af[mi][2]), "r"(af[mi][3]),
                          "r"(bf[ni][0]), "r"(bf[ni][1]));
                }
        }
    }

    // ---- epilogue: + residual[id, 512+col] -> out[t, 512+col] ----
    #pragma unroll
    for (int mi = 0; mi < 4; mi++) {
        const int lr0 = wm * 64 + mi * 16 + g;
        const int t0  = bm * BM + lr0;
        const int id0 = sids[lr0];
        const int id1 = sids[lr0 + 8];
        #pragma unroll
        for (int ni = 0; ni < 4; ni++) {
            const int col = bn * BN + wn * 32 + ni * 8 + tg * 2;
            {
                float2 rv = *reinterpret_cast<const float2*>(
                    residual + (size_t)id0 * LARGEN + SMALLN + col);
                float2 o;
                o.x = acc[mi][ni][0] + rv.x;
                o.y = acc[mi][ni][1] + rv.y;
                *reinterpret_cast<float2*>(
                    out + (size_t)t0 * LARGEN + SMALLN + col) = o;
            }
            {
                float2 rv = *reinterpret_cast<const float2*>(
                    residual + (size_t)id1 * LARGEN + SMALLN + col);
                float2 o;
                o.x = acc[mi][ni][2] + rv.x;
                o.y = acc[mi][ni][3] + rv.y;
                *reinterpret_cast<float2*>(
                    out + (size_t)(t0 + 8) * LARGEN + SMALLN + col) = o;
            }
        }
    }
}

// ---------------------------------------------------------------------------
// Launch
// ---------------------------------------------------------------------------
extern "C" void kernel_launch(void* const* d_in, const int* in_sizes, int n_in,
                              void* d_out, int out_size) {
    const int*   ids      = (const int*)  d_in[0];  // [4,2048]
    const float* weight   = (const float*)d_in[1];  // [50257,512]
    const float* cw       = (const float*)d_in[2];  // [512,512]
    const float* residual = (const float*)d_in[3];  // [50257,1024]
    float* out = (float*)d_out;                     // [8192,1024]

    cudaFuncSetAttribute(gemm_second_half,
                         cudaFuncAttributeMaxDynamicSharedMemorySize, SMEM_BYTES);

    // merged prep: gather+add first half, stage Abf, convert cw
    {
        int total = GATHER_UNITS + CW_UNITS;        // 1,114,112
        prep_kernel<<<total / 256, 256>>>(
            ids,
            reinterpret_cast<const float4*>(weight),
            reinterpret_cast<const float4*>(residual),
            reinterpret_cast<const float4*>(cw),
            reinterpret_cast<float4*>(out));
    }

    // pipelined GEMM + residual epilogue (one wave: 128 CTAs)
    {
        dim3 grid(SMALLN / BN, NTOK / BM);          // (4, 32)
        gemm_second_half<<<grid, 512, SMEM_BYTES>>>(ids, residual, out);
    }
}